// round 17
// baseline (speedup 1.0000x reference)
#include <cuda_runtime.h>
#include <math.h>

#define S_ 8192
#define D_ 64
#define N_ 2048
#define O_ 8
#define NBLK 512        // 4 blocks/SM via __launch_bounds__(256,4): regs<=64,
#define NTHR 256        // capacity 592 >= 512 -> ALL blocks co-resident

// ---- scratch (allocation-free rule: __device__ globals; BSS = 0) ----
// partial SUMS (not logs): phase 2 combines halves with log(p0+p1).
__device__ float d_p0[N_];        // w0 full-row expsums
__device__ float d_p1[2 * N_];    // w1 half-row partials [row*2 + half]
__device__ float d_p2[2 * N_];    // w2 half-row partials
__device__ float d_po[2 * O_];    // w_out half-row partials
__device__ __align__(128) unsigned d_done;    // phase-1 arrivals
__device__ __align__(128) unsigned d_gdone;   // end arrivals (reset)
__device__ unsigned d_flags[NBLK * 32];       // one 128B line per block

static __device__ __forceinline__ unsigned ld_acq(const unsigned* p) {
    unsigned v; asm volatile("ld.acquire.gpu.u32 %0,[%1];" : "=r"(v) : "l"(p)); return v;
}
static __device__ __forceinline__ void st_rel(unsigned* p, unsigned v) {
    asm volatile("st.release.gpu.u32 [%0],%1;" :: "l"(p), "r"(v) : "memory");
}
static __device__ __forceinline__ float warp_sum(float v) {
    #pragma unroll
    for (int off = 16; off; off >>= 1) v += __shfl_xor_sync(0xffffffffu, v, off);
    return v;
}
// sum(exp(half-row[0..1023])). 8 float4 in flight per lane (32 regs - fits the
// 64-reg budget; this is the MLP that R16's 32-reg cap destroyed). No max pass
// (weights N(0,1); validated rel_err 5.8e-7 in R15/R16).
static __device__ __forceinline__ float half_expsum(const float* __restrict__ p,
                                                    int lane) {
    const float4* r4 = (const float4*)p;
    float4 v[8];
    #pragma unroll
    for (int i = 0; i < 8; i++) v[i] = r4[i * 32 + lane];
    float a0 = 0.f, a1 = 0.f, a2 = 0.f, a3 = 0.f;
    #pragma unroll
    for (int i = 0; i < 8; i++) {
        a0 += __expf(v[i].x); a1 += __expf(v[i].y);
        a2 += __expf(v[i].z); a3 += __expf(v[i].w);
    }
    return warp_sum((a0 + a1) + (a2 + a3));
}

// ---------------------------------------------------------------------------
// Fused persistent kernel, v3:
//   warps 0-3 : 128 path walks (chain in regs across barrier) + 1 w0 row each
//               + stage 16 x rows to smem
//   warps 4-7 : 4 half-row expsums each (block's 16 units contiguous in DRAM);
//               blocks 0-3 also cover the 16 w_out half-rows
// Totals: 512*128 = 65536 paths; 512*4*4 = 8192 = w1+w2 half-rows; 512*4 =
// 2048 w0 rows. Phase 2 (walkers only): 7 L2 sector reads + 4 logs + outputs.
// ---------------------------------------------------------------------------
__global__ void __launch_bounds__(NTHR, 4) occamnet_fused(const float* __restrict__ x,
                                                          const float* __restrict__ w0,
                                                          const float* __restrict__ w1,
                                                          const float* __restrict__ w2,
                                                          const float* __restrict__ w_out,
                                                          const int* __restrict__ c0,
                                                          const int* __restrict__ c1,
                                                          const int* __restrict__ c2,
                                                          const int* __restrict__ keys_out,
                                                          float* __restrict__ out)
{
    __shared__ float s_x[16 * D_];      // 4 KB: this block's 16 sample rows
    __shared__ unsigned s_arr;

    const int b = blockIdx.x;
    const int t = threadIdx.x;
    const int lane = t & 31;
    const int warp = t >> 5;

    int r2 = 0, r1 = 0, r0 = 0, cin = 0;
    float lp = 0.f;

    if (warp < 4) {
        // ================= walker =================
        const int tid = b * 128 + t;              // t in [0,128)
        const int s = tid >> 3;
        const int o = tid & 7;

        r2 = keys_out[tid];                       // round 0 (coalesced)

        // independent work while round 0 is in flight:
        const float4* x4 = (const float4*)(x + (size_t)b * 16 * D_);
        ((float4*)s_x)[t]       = x4[t];          // stage 16 x rows
        ((float4*)s_x)[t + 128] = x4[t + 128];
        const int w0r = b * 4 + warp;             // one w0 row per walk warp
        const float* wr = w0 + (size_t)w0r * D_;
        float sc = __expf(wr[lane]) + __expf(wr[lane + 32]);
        sc = warp_sum(sc);
        if (lane == 0) d_p0[w0r] = sc;

        // dependent chain (stays in registers across the barrier)
        lp = w_out[o * N_ + r2];
        r1 = c2[(size_t)s * N_ + r2];
        lp += w2[(size_t)r2 * N_ + r1];
        r0 = c1[(size_t)s * N_ + r1];
        lp += w1[(size_t)r1 * N_ + r0];
        cin = c0[(size_t)s * N_ + r0];
        lp += w0[r0 * D_ + cin];
    } else {
        // ================= streamer: 4 contiguous half-row units =================
        const int base = (b * 4 + (warp - 4)) * 4;
        #pragma unroll
        for (int u = 0; u < 4; u++) {
            const int unit = base + u;
            const float* src;
            float* dst;
            if (unit < 2 * N_) {
                src = w1 + (size_t)(unit >> 1) * N_ + (unit & 1) * 1024;
                dst = &d_p1[unit];
            } else {
                const int v2 = unit - 2 * N_;
                src = w2 + (size_t)(v2 >> 1) * N_ + (v2 & 1) * 1024;
                dst = &d_p2[v2];
            }
            const float sv = half_expsum(src, lane);
            if (lane == 0) *dst = sv;
        }
        if (b < 4) {                              // 16 w_out half-rows
            const int unit = b * 4 + (warp - 4);
            const float* src = w_out + (size_t)(unit >> 1) * N_ + (unit & 1) * 1024;
            const float sv = half_expsum(src, lane);
            if (lane == 0) d_po[unit] = sv;
        }
    }

    // ================= grid barrier (all 512 blocks resident) =================
    __syncthreads();
    if (t == 0) { __threadfence(); s_arr = atomicAdd(&d_done, 1u); }
    __syncthreads();
    if (s_arr == NBLK - 1) {                      // last block: 512-flag broadcast
        st_rel(&d_flags[t * 32], 1u);
        st_rel(&d_flags[(t + NTHR) * 32], 1u);
    }
    if (t == 0) {
        while (ld_acq(&d_flags[b * 32]) == 0u) __nanosleep(64);
        d_flags[b * 32] = 0u;                     // self-reset for next replay
    }
    __syncthreads();

    // ================= phase 2: walkers combine partials + write =================
    if (warp < 4) {
        const int tid = b * 128 + t;
        const int o = tid & 7;
        const float lse = __logf(__ldcg(&d_po[2 * o])  + __ldcg(&d_po[2 * o + 1]))
                        + __logf(__ldcg(&d_p2[2 * r2]) + __ldcg(&d_p2[2 * r2 + 1]))
                        + __logf(__ldcg(&d_p1[2 * r1]) + __ldcg(&d_p1[2 * r1 + 1]))
                        + __logf(__ldcg(&d_p0[r0]));
        out[S_ * O_ + tid] = __expf(lp - lse);            // [1, S, O] slice
        const float xv = s_x[(t >> 3) * D_ + cin];
        out[tid] = __sinf(__sinf(__sinf(xv)));            // [0, S, O] slice
    }

    // counter reset for the next graph replay
    __syncthreads();
    if (t == 0) {
        unsigned old = atomicAdd(&d_gdone, 1u);
        if (old == NBLK - 1) {
            atomicExch(&d_done, 0u);
            atomicExch(&d_gdone, 0u);
        }
    }
}

extern "C" void kernel_launch(void* const* d_in, const int* in_sizes, int n_in,
                              void* d_out, int out_size)
{
    const float* x     = (const float*)d_in[0];
    const float* w0    = (const float*)d_in[1];
    const float* w1    = (const float*)d_in[2];
    const float* w2    = (const float*)d_in[3];
    const float* w_out = (const float*)d_in[4];
    const int*   c0    = (const int*)d_in[5];
    const int*   c1    = (const int*)d_in[6];
    const int*   c2    = (const int*)d_in[7];
    const int*   keys  = (const int*)d_in[8];
    float*       out   = (float*)d_out;

    occamnet_fused<<<NBLK, NTHR>>>(x, w0, w1, w2, w_out, c0, c1, c2, keys, out);
}